// round 4
// baseline (speedup 1.0000x reference)
#include <cuda_runtime.h>

#define BB 4
#define HH 16
#define SS 4096
#define DD 64
#define NBH (BB*HH)
#define NCHUNK 8
#define EPS 1e-6f

__device__ float g_kv[NBH * DD * DD];             // [bh][d][f] (final)
__device__ float g_kvp[NCHUNK * NBH * DD * DD];   // per-chunk partials
__device__ float g_ksum[NBH * DD];                // [bh][d]
__device__ int   g_mask_fmt;                      // 0 = 4-byte elems, 1 = 1-byte

// ---------- helpers ----------
__device__ __forceinline__ float fmap(float x) {
    return x > 0.0f ? x + 1.0f : __expf(x);
}

__device__ __forceinline__ void fma2(unsigned long long &acc,
                                     unsigned long long a,
                                     unsigned long long b) {
    asm("fma.rn.f32x2 %0, %1, %2, %0;" : "+l"(acc) : "l"(a), "l"(b));
}

__device__ __forceinline__ unsigned long long packf2(float x, float y) {
    unsigned long long r;
    asm("mov.b64 %0, {%1, %2};" : "=l"(r) : "f"(x), "f"(y));
    return r;
}

__device__ __forceinline__ float2 unpackf2(unsigned long long v) {
    float2 r;
    asm("mov.b64 {%0, %1}, %2;" : "=f"(r.x), "=f"(r.y) : "l"(v));
    return r;
}

__device__ __forceinline__ float get_valid(const void* mask, int fmt, int idx) {
    if (fmt) return ((const unsigned char*)mask)[idx] == 0 ? 1.0f : 0.0f;
    return ((const unsigned int*)mask)[idx] == 0u ? 1.0f : 0.0f;
}

// ---------- small kernels ----------
__global__ void zero_kernel() {
    int idx = blockIdx.x * blockDim.x + threadIdx.x;
    if (idx < NBH * DD) g_ksum[idx] = 0.0f;
    if (idx == 0)       g_mask_fmt = 0;
}

__global__ void detect_kernel(const unsigned int* __restrict__ mask) {
    int idx = blockIdx.x * blockDim.x + threadIdx.x;  // 4096 threads
    unsigned int w = mask[idx];
    if (w != 0u && w != 1u && w != 0x3F800000u) atomicOr(&g_mask_fmt, 1);
}

// Sum the NCHUNK partial kv matrices.
__global__ void __launch_bounds__(256)
reduce_kernel() {
    const int bh = blockIdx.x;
    const int tid = threadIdx.x;
    const float4* src = (const float4*)g_kvp;
    float4* dst = (float4*)(g_kv + bh * DD * DD);
#pragma unroll
    for (int r = 0; r < 4; r++) {
        int idx = r * 256 + tid;            // float4 idx within 4096 floats
        float4 s = src[(size_t)bh * 1024 + idx];
#pragma unroll
        for (int c = 1; c < NCHUNK; c++) {
            float4 t = src[(size_t)(c * NBH + bh) * 1024 + idx];
            s.x += t.x; s.y += t.y; s.z += t.z; s.w += t.w;
        }
        dst[idx] = s;
    }
}

// ---------- Pass 1 ----------
// grid (NCHUNK, 64), 256 threads = 4 groups of 64, each group 8d x 8f tile.
// Each block handles 512 tokens; stages of 64 tokens in smem.
__global__ void __launch_bounds__(256)
pass1_kernel(const float* __restrict__ kk, const float* __restrict__ vv,
             const void* __restrict__ mask) {
    __shared__ float sm[8192];       // ksh[0..4096), vsh[4096..8192) : 32KB
    float* ksh = sm;
    float* vsh = sm + 4096;

    const int bh  = blockIdx.y;
    const int s0  = blockIdx.x * 512;
    const int tid = threadIdx.x;
    const int g   = tid >> 6;        // group 0..3
    const int lt  = tid & 63;
    const int i   = lt & 7;          // d group
    const int j   = lt >> 3;         // f group
    const int fmt = g_mask_fmt;
    const int b   = bh >> 4;

    unsigned long long acc[8][4];
#pragma unroll
    for (int a = 0; a < 8; a++)
#pragma unroll
        for (int p = 0; p < 4; p++) acc[a][p] = 0ull;
    float ks[8];
#pragma unroll
    for (int a = 0; a < 8; a++) ks[a] = 0.f;

    const float4* kg = (const float4*)(kk + (size_t)bh * SS * DD);
    const float4* vg = (const float4*)(vv + (size_t)bh * SS * DD);

    for (int st = 0; st < 8; st++) {
        const int sbase = s0 + st * 64;
        __syncthreads();
#pragma unroll
        for (int it = 0; it < 4; it++) {
            int vi = it * 256 + tid;        // float4 index in 64x64 tile
            int sl = vi >> 4;
            int c4 = vi & 15;
            float valid = get_valid(mask, fmt, b * SS + sbase + sl);
            float4 k4 = kg[(size_t)(sbase + sl) * 16 + c4];
            float4 v4 = vg[(size_t)(sbase + sl) * 16 + c4];
            k4.x = fmap(k4.x) * valid;
            k4.y = fmap(k4.y) * valid;
            k4.z = fmap(k4.z) * valid;
            k4.w = fmap(k4.w) * valid;
            ((float4*)ksh)[vi] = k4;
            ((float4*)vsh)[vi] = v4;
        }
        __syncthreads();

        // compute 16 tokens, software-pipelined 1-deep
        const int base = g * 16;
        float4 ka = *(const float4*)(ksh + (base) * 64 + 4 * i);
        float4 kb = *(const float4*)(ksh + (base) * 64 + 32 + 4 * i);
        ulonglong2 va = *(const ulonglong2*)(vsh + (base) * 64 + 4 * j);
        ulonglong2 vb = *(const ulonglong2*)(vsh + (base) * 64 + 32 + 4 * j);
#pragma unroll
        for (int m = 0; m < 16; m++) {
            float4 nka, nkb; ulonglong2 nva, nvb;
            if (m < 15) {
                const int sl = base + m + 1;
                nka = *(const float4*)(ksh + sl * 64 + 4 * i);
                nkb = *(const float4*)(ksh + sl * 64 + 32 + 4 * i);
                nva = *(const ulonglong2*)(vsh + sl * 64 + 4 * j);
                nvb = *(const ulonglong2*)(vsh + sl * 64 + 32 + 4 * j);
            }
            float kd[8] = {ka.x, ka.y, ka.z, ka.w, kb.x, kb.y, kb.z, kb.w};
#pragma unroll
            for (int a = 0; a < 8; a++) {
                unsigned long long qp = packf2(kd[a], kd[a]);
                fma2(acc[a][0], qp, va.x);
                fma2(acc[a][1], qp, va.y);
                fma2(acc[a][2], qp, vb.x);
                fma2(acc[a][3], qp, vb.y);
            }
            if (j == 0) {
#pragma unroll
                for (int a = 0; a < 8; a++) ks[a] += kd[a];
            }
            ka = nka; kb = nkb; va = nva; vb = nvb;
        }
    }

    // tree-reduce 4 groups -> group 0 (buf = 4096 ull = 32KB, exactly sm)
    __syncthreads();
    unsigned long long* buf = (unsigned long long*)sm;
    if (g == 1 || g == 3) {
        unsigned long long* w = buf + ((g >> 1) * 64 + lt) * 32;
#pragma unroll
        for (int a = 0; a < 8; a++)
#pragma unroll
            for (int p = 0; p < 4; p++) w[a * 4 + p] = acc[a][p];
    }
    __syncthreads();
    if (g == 0 || g == 2) {
        const unsigned long long* w = buf + ((g >> 1) * 64 + lt) * 32;
#pragma unroll
        for (int a = 0; a < 8; a++)
#pragma unroll
            for (int p = 0; p < 4; p++) {
                float2 x = unpackf2(acc[a][p]);
                float2 y = unpackf2(w[a * 4 + p]);
                acc[a][p] = packf2(x.x + y.x, x.y + y.y);
            }
    }
    __syncthreads();
    if (g == 2) {
        unsigned long long* w = buf + lt * 32;
#pragma unroll
        for (int a = 0; a < 8; a++)
#pragma unroll
            for (int p = 0; p < 4; p++) w[a * 4 + p] = acc[a][p];
    }
    __syncthreads();
    if (g == 0) {
        const unsigned long long* w = buf + lt * 32;
        float* dst = g_kvp + (size_t)(blockIdx.x * NBH + bh) * DD * DD;
#pragma unroll
        for (int a = 0; a < 8; a++) {
            const int d = (a < 4) ? (4 * i + a) : (32 + 4 * i + a - 4);
            float2 r0 = unpackf2(acc[a][0]); float2 s0 = unpackf2(w[a * 4 + 0]);
            float2 r1 = unpackf2(acc[a][1]); float2 s1 = unpackf2(w[a * 4 + 1]);
            float2 r2 = unpackf2(acc[a][2]); float2 s2 = unpackf2(w[a * 4 + 2]);
            float2 r3 = unpackf2(acc[a][3]); float2 s3 = unpackf2(w[a * 4 + 3]);
            float4 lo, hi;
            lo.x = r0.x + s0.x; lo.y = r0.y + s0.y;
            lo.z = r1.x + s1.x; lo.w = r1.y + s1.y;
            hi.x = r2.x + s2.x; hi.y = r2.y + s2.y;
            hi.z = r3.x + s3.x; hi.w = r3.y + s3.y;
            *(float4*)(dst + d * 64 + 4 * j)      = lo;
            *(float4*)(dst + d * 64 + 32 + 4 * j) = hi;
        }
    }
    if (j == 0) {
        float* kss = g_ksum + bh * DD;
#pragma unroll
        for (int a = 0; a < 8; a++) {
            const int d = (a < 4) ? (4 * i + a) : (32 + 4 * i + a - 4);
            atomicAdd(&kss[d], ks[a]);
        }
    }
}

// ---------- Pass 2 ----------
// grid (32, 64), 128 threads, 128 tokens/block, thread tile 8t x 8f.
__global__ void __launch_bounds__(128)
pass2_kernel(const float* __restrict__ qq, float* __restrict__ out) {
    __shared__ float qsh[64 * 128];   // [d][t]
    __shared__ float kvsh[64 * 64];   // [d][f]
    __shared__ float kss[64];
    __shared__ float zsh[128];

    const int bh  = blockIdx.y;
    const int t0  = blockIdx.x * 128;
    const int tid = threadIdx.x;

    const float4* kvg = (const float4*)(g_kv + bh * DD * DD);
#pragma unroll
    for (int it = 0; it < 8; it++)
        ((float4*)kvsh)[it * 128 + tid] = kvg[it * 128 + tid];
    if (tid < 16)
        ((float4*)kss)[tid] = ((const float4*)(g_ksum + bh * DD))[tid];

    const float4* qg = (const float4*)(qq + (size_t)bh * SS * DD + (size_t)t0 * DD);
    float4 qr[16];
#pragma unroll
    for (int c = 0; c < 16; c++) {
        float4 x = qg[tid * 16 + c];
        x.x = fmap(x.x); x.y = fmap(x.y); x.z = fmap(x.z); x.w = fmap(x.w);
        qr[c] = x;
    }
    __syncthreads();

    float z = EPS;
#pragma unroll
    for (int c = 0; c < 16; c++) {
        z += qr[c].x * kss[4 * c] + qr[c].y * kss[4 * c + 1]
           + qr[c].z * kss[4 * c + 2] + qr[c].w * kss[4 * c + 3];
    }
    zsh[tid] = 1.0f / z;

#pragma unroll
    for (int c = 0; c < 16; c++) {
        qsh[(4 * c + 0) * 128 + tid] = qr[c].x;
        qsh[(4 * c + 1) * 128 + tid] = qr[c].y;
        qsh[(4 * c + 2) * 128 + tid] = qr[c].z;
        qsh[(4 * c + 3) * 128 + tid] = qr[c].w;
    }
    __syncthreads();

    const int ty = tid >> 3;   // 0..15
    const int tx = tid & 7;    // 0..7

    unsigned long long acc[8][4];
#pragma unroll
    for (int r = 0; r < 8; r++)
#pragma unroll
        for (int p = 0; p < 4; p++) acc[r][p] = 0ull;

#pragma unroll 8
    for (int d = 0; d < 64; d++) {
        float4 qa = *(const float4*)(qsh + d * 128 + 4 * ty);
        float4 qb = *(const float4*)(qsh + d * 128 + 64 + 4 * ty);
        ulonglong2 va = *(const ulonglong2*)(kvsh + d * 64 + 4 * tx);
        ulonglong2 vb = *(const ulonglong2*)(kvsh + d * 64 + 32 + 4 * tx);
        float qs[8] = {qa.x, qa.y, qa.z, qa.w, qb.x, qb.y, qb.z, qb.w};
#pragma unroll
        for (int r = 0; r < 8; r++) {
            unsigned long long qp = packf2(qs[r], qs[r]);
            fma2(acc[r][0], qp, va.x);
            fma2(acc[r][1], qp, va.y);
            fma2(acc[r][2], qp, vb.x);
            fma2(acc[r][3], qp, vb.y);
        }
    }

#pragma unroll
    for (int r = 0; r < 8; r++) {
        const int t = (r < 4) ? (4 * ty + r) : (64 + 4 * ty + r - 4);
        const float invz = zsh[t];
        float* og = out + (size_t)bh * SS * DD + (size_t)(t0 + t) * DD;
        float2 a0 = unpackf2(acc[r][0]);
        float2 a1 = unpackf2(acc[r][1]);
        float2 a2 = unpackf2(acc[r][2]);
        float2 a3 = unpackf2(acc[r][3]);
        float4 o0, o1;
        o0.x = a0.x * invz; o0.y = a0.y * invz;
        o0.z = a1.x * invz; o0.w = a1.y * invz;
        o1.x = a2.x * invz; o1.y = a2.y * invz;
        o1.z = a3.x * invz; o1.w = a3.y * invz;
        *(float4*)(og + 4 * tx)      = o0;
        *(float4*)(og + 32 + 4 * tx) = o1;
    }
}

extern "C" void kernel_launch(void* const* d_in, const int* in_sizes, int n_in,
                              void* d_out, int out_size) {
    const float* q = (const float*)d_in[0];
    const float* k = (const float*)d_in[1];
    const float* v = (const float*)d_in[2];
    const void*  m = d_in[3];
    float* out = (float*)d_out;

    zero_kernel<<<16, 256>>>();
    detect_kernel<<<16, 256>>>((const unsigned int*)m);
    pass1_kernel<<<dim3(NCHUNK, NBH), 256>>>(k, v, m);
    reduce_kernel<<<NBH, 256>>>();
    pass2_kernel<<<dim3(SS / 128, NBH), 128>>>(q, out);
}

// round 5
// speedup vs baseline: 1.2895x; 1.2895x over previous
#include <cuda_runtime.h>

#define BB 4
#define HH 16
#define SS 4096
#define DD 64
#define NBH (BB*HH)
#define NCHUNK 16
#define EPS 1e-6f

__device__ float g_kv[NBH * DD * DD];             // [bh][d][f] (final)
__device__ float g_kvp[NCHUNK * NBH * DD * DD];   // per-chunk partials (16MB)
__device__ float g_ksum[NBH * DD];                // [bh][d]
__device__ int   g_mask_fmt;                      // 0 = 4-byte elems, 1 = 1-byte

// ---------- helpers ----------
__device__ __forceinline__ float fmap(float x) {
    return x > 0.0f ? x + 1.0f : __expf(x);
}

__device__ __forceinline__ void fma2(unsigned long long &acc,
                                     unsigned long long a,
                                     unsigned long long b) {
    asm("fma.rn.f32x2 %0, %1, %2, %0;" : "+l"(acc) : "l"(a), "l"(b));
}

__device__ __forceinline__ unsigned long long packf2(float x, float y) {
    unsigned long long r;
    asm("mov.b64 %0, {%1, %2};" : "=l"(r) : "f"(x), "f"(y));
    return r;
}

__device__ __forceinline__ float2 unpackf2(unsigned long long v) {
    float2 r;
    asm("mov.b64 {%0, %1}, %2;" : "=f"(r.x), "=f"(r.y) : "l"(v));
    return r;
}

__device__ __forceinline__ float get_valid(const void* mask, int fmt, int idx) {
    if (fmt) return ((const unsigned char*)mask)[idx] == 0 ? 1.0f : 0.0f;
    return ((const unsigned int*)mask)[idx] == 0u ? 1.0f : 0.0f;
}

// ---------- small kernels ----------
__global__ void zero_kernel() {
    int idx = blockIdx.x * blockDim.x + threadIdx.x;
    if (idx < NBH * DD) g_ksum[idx] = 0.0f;
    if (idx == 0)       g_mask_fmt = 0;
}

__global__ void detect_kernel(const unsigned int* __restrict__ mask) {
    int idx = blockIdx.x * blockDim.x + threadIdx.x;  // 4096 threads
    unsigned int w = mask[idx];
    if (w != 0u && w != 1u && w != 0x3F800000u) atomicOr(&g_mask_fmt, 1);
}

// Sum the NCHUNK partial kv matrices.
__global__ void __launch_bounds__(256)
reduce_kernel() {
    const int bh = blockIdx.x;
    const int tid = threadIdx.x;
    const float4* src = (const float4*)g_kvp;
    float4* dst = (float4*)(g_kv + bh * DD * DD);
#pragma unroll
    for (int r = 0; r < 4; r++) {
        int idx = r * 256 + tid;            // float4 idx within 4096 floats
        float4 s = src[(size_t)bh * 1024 + idx];
#pragma unroll
        for (int c = 1; c < NCHUNK; c++) {
            float4 t = src[(size_t)(c * NBH + bh) * 1024 + idx];
            s.x += t.x; s.y += t.y; s.z += t.z; s.w += t.w;
        }
        dst[idx] = s;
    }
}

// ---------- Pass 1 ----------
// grid (NCHUNK, 64), 256 threads = 4 groups of 64, each group 8d x 8f tile
// over 8 tokens per 32-token stage. 256 tokens per block. No pipelining.
__global__ void __launch_bounds__(256)
pass1_kernel(const float* __restrict__ kk, const float* __restrict__ vv,
             const void* __restrict__ mask) {
    __shared__ float sm[4096];       // ksh[0..2048), vsh[2048..4096) : 16KB
    float* ksh = sm;
    float* vsh = sm + 2048;

    const int bh  = blockIdx.y;
    const int s0  = blockIdx.x * 256;
    const int tid = threadIdx.x;
    const int g   = tid >> 6;        // group 0..3
    const int lt  = tid & 63;
    const int i   = lt & 7;          // d group
    const int j   = lt >> 3;         // f group
    const int fmt = g_mask_fmt;
    const int b   = bh >> 4;

    unsigned long long acc[8][4];
#pragma unroll
    for (int a = 0; a < 8; a++)
#pragma unroll
        for (int p = 0; p < 4; p++) acc[a][p] = 0ull;
    float ks[8];
#pragma unroll
    for (int a = 0; a < 8; a++) ks[a] = 0.f;

    const float4* kg = (const float4*)(kk + (size_t)bh * SS * DD);
    const float4* vg = (const float4*)(vv + (size_t)bh * SS * DD);

    for (int st = 0; st < 8; st++) {
        const int sbase = s0 + st * 32;
        __syncthreads();
#pragma unroll
        for (int it = 0; it < 2; it++) {
            int vi = it * 256 + tid;        // float4 index in 32x64 tile
            int sl = vi >> 4;
            int c4 = vi & 15;
            float valid = get_valid(mask, fmt, b * SS + sbase + sl);
            float4 k4 = kg[(size_t)(sbase + sl) * 16 + c4];
            float4 v4 = vg[(size_t)(sbase + sl) * 16 + c4];
            k4.x = fmap(k4.x) * valid;
            k4.y = fmap(k4.y) * valid;
            k4.z = fmap(k4.z) * valid;
            k4.w = fmap(k4.w) * valid;
            ((float4*)ksh)[vi] = k4;
            ((float4*)vsh)[vi] = v4;
        }
        __syncthreads();

        // this group's 8 tokens
#pragma unroll
        for (int m = 0; m < 8; m++) {
            const int sl = g * 8 + m;
            float4 ka = *(const float4*)(ksh + sl * 64 + 4 * i);
            float4 kb = *(const float4*)(ksh + sl * 64 + 32 + 4 * i);
            ulonglong2 va = *(const ulonglong2*)(vsh + sl * 64 + 4 * j);
            ulonglong2 vb = *(const ulonglong2*)(vsh + sl * 64 + 32 + 4 * j);
            float kd[8] = {ka.x, ka.y, ka.z, ka.w, kb.x, kb.y, kb.z, kb.w};
#pragma unroll
            for (int a = 0; a < 8; a++) {
                unsigned long long qp = packf2(kd[a], kd[a]);
                fma2(acc[a][0], qp, va.x);
                fma2(acc[a][1], qp, va.y);
                fma2(acc[a][2], qp, vb.x);
                fma2(acc[a][3], qp, vb.y);
            }
            if (j == 0) {
#pragma unroll
                for (int a = 0; a < 8; a++) ks[a] += kd[a];
            }
        }
    }

    // sequential tree reduce: g1->g0, g3->g2, g2->g0. buf = 2048 ull = 16KB.
    unsigned long long* buf = (unsigned long long*)sm;
    __syncthreads();
    if (g == 1) {
        unsigned long long* w = buf + lt * 32;
#pragma unroll
        for (int a = 0; a < 8; a++)
#pragma unroll
            for (int p = 0; p < 4; p++) w[a * 4 + p] = acc[a][p];
    }
    __syncthreads();
    if (g == 0) {
        const unsigned long long* w = buf + lt * 32;
#pragma unroll
        for (int a = 0; a < 8; a++)
#pragma unroll
            for (int p = 0; p < 4; p++) {
                float2 x = unpackf2(acc[a][p]);
                float2 y = unpackf2(w[a * 4 + p]);
                acc[a][p] = packf2(x.x + y.x, x.y + y.y);
            }
    }
    __syncthreads();
    if (g == 3) {
        unsigned long long* w = buf + lt * 32;
#pragma unroll
        for (int a = 0; a < 8; a++)
#pragma unroll
            for (int p = 0; p < 4; p++) w[a * 4 + p] = acc[a][p];
    }
    __syncthreads();
    if (g == 2) {
        const unsigned long long* w = buf + lt * 32;
#pragma unroll
        for (int a = 0; a < 8; a++)
#pragma unroll
            for (int p = 0; p < 4; p++) {
                float2 x = unpackf2(acc[a][p]);
                float2 y = unpackf2(w[a * 4 + p]);
                acc[a][p] = packf2(x.x + y.x, x.y + y.y);
            }
    }
    __syncthreads();
    if (g == 2) {
        unsigned long long* w = buf + lt * 32;
#pragma unroll
        for (int a = 0; a < 8; a++)
#pragma unroll
            for (int p = 0; p < 4; p++) w[a * 4 + p] = acc[a][p];
    }
    __syncthreads();
    if (g == 0) {
        const unsigned long long* w = buf + lt * 32;
        float* dst = g_kvp + (size_t)(blockIdx.x * NBH + bh) * DD * DD;
#pragma unroll
        for (int a = 0; a < 8; a++) {
            const int d = (a < 4) ? (4 * i + a) : (32 + 4 * i + a - 4);
            float2 r0 = unpackf2(acc[a][0]); float2 s0v = unpackf2(w[a * 4 + 0]);
            float2 r1 = unpackf2(acc[a][1]); float2 s1v = unpackf2(w[a * 4 + 1]);
            float2 r2 = unpackf2(acc[a][2]); float2 s2v = unpackf2(w[a * 4 + 2]);
            float2 r3 = unpackf2(acc[a][3]); float2 s3v = unpackf2(w[a * 4 + 3]);
            float4 lo, hi;
            lo.x = r0.x + s0v.x; lo.y = r0.y + s0v.y;
            lo.z = r1.x + s1v.x; lo.w = r1.y + s1v.y;
            hi.x = r2.x + s2v.x; hi.y = r2.y + s2v.y;
            hi.z = r3.x + s3v.x; hi.w = r3.y + s3v.y;
            *(float4*)(dst + d * 64 + 4 * j)      = lo;
            *(float4*)(dst + d * 64 + 32 + 4 * j) = hi;
        }
    }
    if (j == 0) {
        float* kss = g_ksum + bh * DD;
#pragma unroll
        for (int a = 0; a < 8; a++) {
            const int d = (a < 4) ? (4 * i + a) : (32 + 4 * i + a - 4);
            atomicAdd(&kss[d], ks[a]);
        }
    }
}

// ---------- Pass 2 ---------- (identical to round-3 winner)
// grid (32, 64), 128 threads, 128 tokens/block, thread tile 8t x 8f.
__global__ void __launch_bounds__(128)
pass2_kernel(const float* __restrict__ qq, float* __restrict__ out) {
    __shared__ float qsh[64 * 128];   // [d][t]
    __shared__ float kvsh[64 * 64];   // [d][f]
    __shared__ float kss[64];
    __shared__ float zsh[128];

    const int bh  = blockIdx.y;
    const int t0  = blockIdx.x * 128;
    const int tid = threadIdx.x;

    const float4* kvg = (const float4*)(g_kv + bh * DD * DD);
#pragma unroll
    for (int it = 0; it < 8; it++)
        ((float4*)kvsh)[it * 128 + tid] = kvg[it * 128 + tid];
    if (tid < 16)
        ((float4*)kss)[tid] = ((const float4*)(g_ksum + bh * DD))[tid];

    const float4* qg = (const float4*)(qq + (size_t)bh * SS * DD + (size_t)t0 * DD);
    float4 qr[16];
#pragma unroll
    for (int c = 0; c < 16; c++) {
        float4 x = qg[tid * 16 + c];
        x.x = fmap(x.x); x.y = fmap(x.y); x.z = fmap(x.z); x.w = fmap(x.w);
        qr[c] = x;
    }
    __syncthreads();

    float z = EPS;
#pragma unroll
    for (int c = 0; c < 16; c++) {
        z += qr[c].x * kss[4 * c] + qr[c].y * kss[4 * c + 1]
           + qr[c].z * kss[4 * c + 2] + qr[c].w * kss[4 * c + 3];
    }
    zsh[tid] = 1.0f / z;

#pragma unroll
    for (int c = 0; c < 16; c++) {
        qsh[(4 * c + 0) * 128 + tid] = qr[c].x;
        qsh[(4 * c + 1) * 128 + tid] = qr[c].y;
        qsh[(4 * c + 2) * 128 + tid] = qr[c].z;
        qsh[(4 * c + 3) * 128 + tid] = qr[c].w;
    }
    __syncthreads();

    const int ty = tid >> 3;   // 0..15
    const int tx = tid & 7;    // 0..7

    unsigned long long acc[8][4];
#pragma unroll
    for (int r = 0; r < 8; r++)
#pragma unroll
        for (int p = 0; p < 4; p++) acc[r][p] = 0ull;

#pragma unroll 4
    for (int d = 0; d < 64; d++) {
        float4 qa = *(const float4*)(qsh + d * 128 + 4 * ty);
        float4 qb = *(const float4*)(qsh + d * 128 + 64 + 4 * ty);
        ulonglong2 va = *(const ulonglong2*)(kvsh + d * 64 + 4 * tx);
        ulonglong2 vb = *(const ulonglong2*)(kvsh + d * 64 + 32 + 4 * tx);
        float qs[8] = {qa.x, qa.y, qa.z, qa.w, qb.x, qb.y, qb.z, qb.w};
#pragma unroll
        for (int r = 0; r < 8; r++) {
            unsigned long long qp = packf2(qs[r], qs[r]);
            fma2(acc[r][0], qp, va.x);
            fma2(acc[r][1], qp, va.y);
            fma2(acc[r][2], qp, vb.x);
            fma2(acc[r][3], qp, vb.y);
        }
    }

#pragma unroll
    for (int r = 0; r < 8; r++) {
        const int t = (r < 4) ? (4 * ty + r) : (64 + 4 * ty + r - 4);
        const float invz = zsh[t];
        float* og = out + (size_t)bh * SS * DD + (size_t)(t0 + t) * DD;
        float2 a0 = unpackf2(acc[r][0]);
        float2 a1 = unpackf2(acc[r][1]);
        float2 a2 = unpackf2(acc[r][2]);
        float2 a3 = unpackf2(acc[r][3]);
        float4 o0, o1;
        o0.x = a0.x * invz; o0.y = a0.y * invz;
        o0.z = a1.x * invz; o0.w = a1.y * invz;
        o1.x = a2.x * invz; o1.y = a2.y * invz;
        o1.z = a3.x * invz; o1.w = a3.y * invz;
        *(float4*)(og + 4 * tx)      = o0;
        *(float4*)(og + 32 + 4 * tx) = o1;
    }
}

extern "C" void kernel_launch(void* const* d_in, const int* in_sizes, int n_in,
                              void* d_out, int out_size) {
    const float* q = (const float*)d_in[0];
    const float* k = (const float*)d_in[1];
    const float* v = (const float*)d_in[2];
    const void*  m = d_in[3];
    float* out = (float*)d_out;

    zero_kernel<<<16, 256>>>();
    detect_kernel<<<16, 256>>>((const unsigned int*)m);
    pass1_kernel<<<dim3(NCHUNK, NBH), 256>>>(k, v, m);
    reduce_kernel<<<NBH, 256>>>();
    pass2_kernel<<<dim3(SS / 128, NBH), 128>>>(q, out);
}

// round 6
// speedup vs baseline: 1.5625x; 1.2117x over previous
#include <cuda_runtime.h>

#define BB 4
#define HH 16
#define SS 4096
#define DD 64
#define NBH (BB*HH)
#define NCHUNK 8
#define EPS 1e-6f

__device__ float g_kv[NBH * DD * DD];             // [bh][d][f] (final)
__device__ float g_kvp[NCHUNK * NBH * DD * DD];   // per-chunk partials (8MB)
__device__ float g_ksum[NBH * DD];                // [bh][d]
__device__ int   g_mask_fmt;                      // 0 = 4-byte elems, 1 = 1-byte

// ---------- helpers ----------
__device__ __forceinline__ float fmap(float x) {
    return x > 0.0f ? x + 1.0f : __expf(x);
}

__device__ __forceinline__ void fma2(unsigned long long &acc,
                                     unsigned long long a,
                                     unsigned long long b) {
    asm("fma.rn.f32x2 %0, %1, %2, %0;" : "+l"(acc) : "l"(a), "l"(b));
}

__device__ __forceinline__ unsigned long long packf2(float x, float y) {
    unsigned long long r;
    asm("mov.b64 %0, {%1, %2};" : "=l"(r) : "f"(x), "f"(y));
    return r;
}

__device__ __forceinline__ float2 unpackf2(unsigned long long v) {
    float2 r;
    asm("mov.b64 {%0, %1}, %2;" : "=f"(r.x), "=f"(r.y) : "l"(v));
    return r;
}

__device__ __forceinline__ float get_valid(const void* mask, int fmt, int idx) {
    if (fmt) return ((const unsigned char*)mask)[idx] == 0 ? 1.0f : 0.0f;
    return ((const unsigned int*)mask)[idx] == 0u ? 1.0f : 0.0f;
}

// ---------- small kernels ----------
__global__ void zero_kernel() {
    int idx = blockIdx.x * blockDim.x + threadIdx.x;
    if (idx < NBH * DD) g_ksum[idx] = 0.0f;
    if (idx == 0)       g_mask_fmt = 0;
}

__global__ void detect_kernel(const unsigned int* __restrict__ mask) {
    int idx = blockIdx.x * blockDim.x + threadIdx.x;  // 4096 threads
    unsigned int w = mask[idx];
    if (w != 0u && w != 1u && w != 0x3F800000u) atomicOr(&g_mask_fmt, 1);
}

// Sum the NCHUNK partial kv matrices. grid 256: (bh, quarter).
__global__ void __launch_bounds__(256)
reduce_kernel() {
    const int bh  = blockIdx.x >> 2;
    const int qt  = blockIdx.x & 3;
    const int tid = threadIdx.x;
    const int idx = qt * 256 + tid;       // float4 idx within 4096 floats
    const float4* src = (const float4*)g_kvp;
    float4* dst = (float4*)(g_kv + bh * DD * DD);
    float4 s = src[(size_t)bh * 1024 + idx];
#pragma unroll
    for (int c = 1; c < NCHUNK; c++) {
        float4 t = src[(size_t)(c * NBH + bh) * 1024 + idx];
        s.x += t.x; s.y += t.y; s.z += t.z; s.w += t.w;
    }
    dst[idx] = s;
}

// ---------- Pass 1 ----------
// grid (NCHUNK, 64), 256 threads. Thread (i,j) owns the DISJOINT tile
// d=4i..4i+3 x f=4j..4j+3; every thread visits every token of the chunk.
// Register-staged double-buffered smem, one __syncthreads per 32-token stage.
__global__ void __launch_bounds__(256)
pass1_kernel(const float* __restrict__ kk, const float* __restrict__ vv,
             const void* __restrict__ mask) {
    __shared__ float ksh[2][2048];
    __shared__ float vsh[2][2048];

    const int bh  = blockIdx.y;
    const int s0  = blockIdx.x * 512;
    const int tid = threadIdx.x;
    const int i   = tid & 15;        // d group
    const int j   = tid >> 4;        // f group
    const int fmt = g_mask_fmt;
    const int b   = bh >> 4;

    const float4* kg = (const float4*)(kk + (size_t)bh * SS * DD);
    const float4* vg = (const float4*)(vv + (size_t)bh * SS * DD);

    unsigned long long acc[4][2];
#pragma unroll
    for (int a = 0; a < 4; a++) { acc[a][0] = 0ull; acc[a][1] = 0ull; }
    float ks[4] = {0.f, 0.f, 0.f, 0.f};

    float4 kr[2], vr[2];

    // prefetch stage 0
    {
        const int sbase = s0;
#pragma unroll
        for (int it = 0; it < 2; it++) {
            int vi = it * 256 + tid;
            int sl = vi >> 4, c4 = vi & 15;
            float valid = get_valid(mask, fmt, b * SS + sbase + sl);
            float4 k4 = kg[(size_t)(sbase + sl) * 16 + c4];
            vr[it] = vg[(size_t)(sbase + sl) * 16 + c4];
            k4.x = fmap(k4.x) * valid;
            k4.y = fmap(k4.y) * valid;
            k4.z = fmap(k4.z) * valid;
            k4.w = fmap(k4.w) * valid;
            kr[it] = k4;
        }
    }

    for (int st = 0; st < 16; st++) {
        const int bufi = st & 1;
        // store current stage regs -> smem
#pragma unroll
        for (int it = 0; it < 2; it++) {
            ((float4*)ksh[bufi])[it * 256 + tid] = kr[it];
            ((float4*)vsh[bufi])[it * 256 + tid] = vr[it];
        }
        __syncthreads();

        // prefetch next stage (overlaps with compute below)
        if (st < 15) {
            const int sbase = s0 + (st + 1) * 32;
#pragma unroll
            for (int it = 0; it < 2; it++) {
                int vi = it * 256 + tid;
                int sl = vi >> 4, c4 = vi & 15;
                float valid = get_valid(mask, fmt, b * SS + sbase + sl);
                float4 k4 = kg[(size_t)(sbase + sl) * 16 + c4];
                vr[it] = vg[(size_t)(sbase + sl) * 16 + c4];
                k4.x = fmap(k4.x) * valid;
                k4.y = fmap(k4.y) * valid;
                k4.z = fmap(k4.z) * valid;
                k4.w = fmap(k4.w) * valid;
                kr[it] = k4;
            }
        }

        // compute 32 tokens from buf
        const float* kb = ksh[bufi];
        const float* vb = vsh[bufi];
#pragma unroll 8
        for (int m = 0; m < 32; m++) {
            float4 kd = *(const float4*)(kb + m * 64 + 4 * i);
            ulonglong2 vd = *(const ulonglong2*)(vb + m * 64 + 4 * j);
            unsigned long long p;
            p = packf2(kd.x, kd.x); fma2(acc[0][0], p, vd.x); fma2(acc[0][1], p, vd.y);
            p = packf2(kd.y, kd.y); fma2(acc[1][0], p, vd.x); fma2(acc[1][1], p, vd.y);
            p = packf2(kd.z, kd.z); fma2(acc[2][0], p, vd.x); fma2(acc[2][1], p, vd.y);
            p = packf2(kd.w, kd.w); fma2(acc[3][0], p, vd.x); fma2(acc[3][1], p, vd.y);
            if (j == 0) {
                ks[0] += kd.x; ks[1] += kd.y; ks[2] += kd.z; ks[3] += kd.w;
            }
        }
        __syncthreads();
    }

    // store this block's partial kv tile (disjoint per thread — plain stores)
    float* dst = g_kvp + (size_t)(blockIdx.x * NBH + bh) * DD * DD;
#pragma unroll
    for (int a = 0; a < 4; a++) {
        float2 lo = unpackf2(acc[a][0]);
        float2 hi = unpackf2(acc[a][1]);
        float4 o;
        o.x = lo.x; o.y = lo.y; o.z = hi.x; o.w = hi.y;
        *(float4*)(dst + (4 * i + a) * 64 + 4 * j) = o;
    }
    if (j == 0) {
        float* kss = g_ksum + bh * DD;
#pragma unroll
        for (int a = 0; a < 4; a++) atomicAdd(&kss[4 * i + a], ks[a]);
    }
}

// ---------- Pass 2 ---------- (round-3 winner, unchanged)
// grid (32, 64), 128 threads, 128 tokens/block, thread tile 8t x 8f.
__global__ void __launch_bounds__(128)
pass2_kernel(const float* __restrict__ qq, float* __restrict__ out) {
    __shared__ float qsh[64 * 128];   // [d][t]
    __shared__ float kvsh[64 * 64];   // [d][f]
    __shared__ float kss[64];
    __shared__ float zsh[128];

    const int bh  = blockIdx.y;
    const int t0  = blockIdx.x * 128;
    const int tid = threadIdx.x;

    const float4* kvg = (const float4*)(g_kv + bh * DD * DD);
#pragma unroll
    for (int it = 0; it < 8; it++)
        ((float4*)kvsh)[it * 128 + tid] = kvg[it * 128 + tid];
    if (tid < 16)
        ((float4*)kss)[tid] = ((const float4*)(g_ksum + bh * DD))[tid];

    const float4* qg = (const float4*)(qq + (size_t)bh * SS * DD + (size_t)t0 * DD);
    float4 qr[16];
#pragma unroll
    for (int c = 0; c < 16; c++) {
        float4 x = qg[tid * 16 + c];
        x.x = fmap(x.x); x.y = fmap(x.y); x.z = fmap(x.z); x.w = fmap(x.w);
        qr[c] = x;
    }
    __syncthreads();

    float z = EPS;
#pragma unroll
    for (int c = 0; c < 16; c++) {
        z += qr[c].x * kss[4 * c] + qr[c].y * kss[4 * c + 1]
           + qr[c].z * kss[4 * c + 2] + qr[c].w * kss[4 * c + 3];
    }
    zsh[tid] = 1.0f / z;

#pragma unroll
    for (int c = 0; c < 16; c++) {
        qsh[(4 * c + 0) * 128 + tid] = qr[c].x;
        qsh[(4 * c + 1) * 128 + tid] = qr[c].y;
        qsh[(4 * c + 2) * 128 + tid] = qr[c].z;
        qsh[(4 * c + 3) * 128 + tid] = qr[c].w;
    }
    __syncthreads();

    const int ty = tid >> 3;   // 0..15
    const int tx = tid & 7;    // 0..7

    unsigned long long acc[8][4];
#pragma unroll
    for (int r = 0; r < 8; r++)
#pragma unroll
        for (int p = 0; p < 4; p++) acc[r][p] = 0ull;

#pragma unroll 4
    for (int d = 0; d < 64; d++) {
        float4 qa = *(const float4*)(qsh + d * 128 + 4 * ty);
        float4 qb = *(const float4*)(qsh + d * 128 + 64 + 4 * ty);
        ulonglong2 va = *(const ulonglong2*)(kvsh + d * 64 + 4 * tx);
        ulonglong2 vb = *(const ulonglong2*)(kvsh + d * 64 + 32 + 4 * tx);
        float qs[8] = {qa.x, qa.y, qa.z, qa.w, qb.x, qb.y, qb.z, qb.w};
#pragma unroll
        for (int r = 0; r < 8; r++) {
            unsigned long long qp = packf2(qs[r], qs[r]);
            fma2(acc[r][0], qp, va.x);
            fma2(acc[r][1], qp, va.y);
            fma2(acc[r][2], qp, vb.x);
            fma2(acc[r][3], qp, vb.y);
        }
    }

#pragma unroll
    for (int r = 0; r < 8; r++) {
        const int t = (r < 4) ? (4 * ty + r) : (64 + 4 * ty + r - 4);
        const float invz = zsh[t];
        float* og = out + (size_t)bh * SS * DD + (size_t)(t0 + t) * DD;
        float2 a0 = unpackf2(acc[r][0]);
        float2 a1 = unpackf2(acc[r][1]);
        float2 a2 = unpackf2(acc[r][2]);
        float2 a3 = unpackf2(acc[r][3]);
        float4 o0, o1;
        o0.x = a0.x * invz; o0.y = a0.y * invz;
        o0.z = a1.x * invz; o0.w = a1.y * invz;
        o1.x = a2.x * invz; o1.y = a2.y * invz;
        o1.z = a3.x * invz; o1.w = a3.y * invz;
        *(float4*)(og + 4 * tx)      = o0;
        *(float4*)(og + 32 + 4 * tx) = o1;
    }
}

extern "C" void kernel_launch(void* const* d_in, const int* in_sizes, int n_in,
                              void* d_out, int out_size) {
    const float* q = (const float*)d_in[0];
    const float* k = (const float*)d_in[1];
    const float* v = (const float*)d_in[2];
    const void*  m = d_in[3];
    float* out = (float*)d_out;

    zero_kernel<<<16, 256>>>();
    detect_kernel<<<16, 256>>>((const unsigned int*)m);
    pass1_kernel<<<dim3(NCHUNK, NBH), 256>>>(k, v, m);
    reduce_kernel<<<NBH * 4, 256>>>();
    pass2_kernel<<<dim3(SS / 128, NBH), 128>>>(q, out);
}